// round 10
// baseline (speedup 1.0000x reference)
#include <cuda_runtime.h>
#include <cuda_bf16.h>
#include <cstdint>

#define N_NODES 17186
#define KTOP    12031
#define BATCH   64
#define NEDGE   500000
#define NTOT    (BATCH * N_NODES)
#define FIN     6
#define H1DIM   64
#define H2DIM   32
#define NSCANB  ((N_NODES + 1023) / 1024)            // 17
#define EPT     4                                    // edges per thread (count/scatter)
#define CNT4B   ((NEDGE / EPT + 255) / 256)          // 489
#define XW0B    ((N_NODES + 15) / 16)                // 1075 (16 nodes per 1024-thr block)
#define H1B     ((N_NODES + 7) / 8)                  // 2149
#define S0B     ((N_NODES + 7) / 8)                  // 2149
#define SRB     ((63 * N_NODES + 255) / 256)         // 4230
#define CXB     ((N_NODES + 255) / 256)              // 68
#define RESTB   ((KTOP + 127) / 128)                 // 94
#define ASTRIDE 72

typedef unsigned long long ull;

// ---------------- device scratch (zero-init at load; each run restores its
// own invariants so graph replays see identical state) ----------------
__device__ int   g_degcnt[N_NODES];        // reset by k_h1 (after all readers)
__device__ int   g_off[N_NODES + 1];
__device__ int   g_cursor[N_NODES];        // reset by k_h1 (after scatter)
__device__ int   g_csr[NEDGE];
__device__ int   g_blksum[32];             // fully overwritten each run
__device__ float g_dinv0[N_NODES];
__device__ float g_xw0[N_NODES * H1DIM];   // dinv0[n]*(x@W1), interleaved [n][lane*2+half]
__device__ float g_h1[N_NODES * H1DIM];    // relu(gcn1), standard [n][c]
__device__ float g_s0w[N_NODES];           // dinv0[n]*(h1@Wp)
__device__ float g_score[NTOT];
__device__ unsigned char g_kept[NTOT];
__device__ int   g_knum[BATCH];            // reset by k_final
__device__ int   g_kidx[63 * KTOP];
__device__ float g_dinv2[N_NODES];
__device__ float g_xpw[N_NODES * H2DIM];   // dinv2[n]*tanh(score)*(h1@W2)
__device__ float g_gmax[BATCH * H2DIM];    // reset by k_final

// ---------------- helpers ----------------
__device__ __forceinline__ bool detect64(const void* ei) {
    const long long* p = (const long long*)ei;
    bool ok = true;
    #pragma unroll
    for (int j = 0; j < 8; j++) {
        long long v = p[j];
        if (v < 0 || v >= N_NODES) ok = false;
    }
    return ok;
}
__device__ __forceinline__ int eidx(const void* ei, bool is64, long long pos) {
    if (is64) return (int)((const long long*)ei)[pos];
    return ((const int*)ei)[pos];
}
__device__ __forceinline__ unsigned okey(float f) {
    unsigned u = __float_as_uint(f);
    u ^= (u & 0x80000000u) ? 0xFFFFFFFFu : 0x80000000u;
    return u;
}
__device__ __forceinline__ ull pack2(float lo, float hi) {
    ull r; asm("mov.b64 %0, {%1, %2};" : "=l"(r) : "f"(lo), "f"(hi)); return r;
}
__device__ __forceinline__ void unpack2(ull v, float& lo, float& hi) {
    asm("mov.b64 {%0, %1}, %2;" : "=f"(lo), "=f"(hi) : "l"(v));
}
__device__ __forceinline__ void ffma2(ull& d, ull a, ull b) {
    asm("fma.rn.f32x2 %0, %1, %2, %0;" : "+l"(d) : "l"(a), "l"(b));
}
__device__ __forceinline__ uint32_t smem_u32(const void* p) {
    uint32_t a;
    asm("{ .reg .u64 t; cvta.to.shared.u64 t, %1; cvt.u32.u64 %0, t; }" : "=r"(a) : "l"(p));
    return a;
}
__device__ __forceinline__ uint32_t bfpack(float a, float b) {
    uint32_t r;
    asm("cvt.rn.bf16x2.f32 %0, %1, %2;" : "=r"(r) : "f"(b), "f"(a));
    return r;
}
__device__ __forceinline__ void mma_bf16(float* c, const uint32_t* a, const uint32_t* b) {
    asm volatile(
        "mma.sync.aligned.m16n8k16.row.col.f32.bf16.bf16.f32 "
        "{%0,%1,%2,%3}, {%4,%5,%6,%7}, {%8,%9}, {%0,%1,%2,%3};"
        : "+f"(c[0]), "+f"(c[1]), "+f"(c[2]), "+f"(c[3])
        : "r"(a[0]), "r"(a[1]), "r"(a[2]), "r"(a[3]), "r"(b[0]), "r"(b[1]));
}
__device__ __forceinline__ void ldmat4(uint32_t* a, uint32_t addr) {
    asm volatile("ldmatrix.sync.aligned.m8n8.x4.shared.b16 {%0,%1,%2,%3}, [%4];"
                 : "=r"(a[0]), "=r"(a[1]), "=r"(a[2]), "=r"(a[3]) : "r"(addr));
}

// ---------------- kernels ----------------
// 4 edges/thread: batch loads first (MLP=4), then independent atomics
__global__ void k_count(const void* ei) {
    bool is64 = detect64(ei);
    int base = (blockIdx.x * blockDim.x + threadIdx.x) * EPT;
    int d[EPT];
    #pragma unroll
    for (int k = 0; k < EPT; k++) {
        int e = base + k;
        d[k] = (e < NEDGE) ? eidx(ei, is64, (long long)NEDGE + e) : -1;
    }
    #pragma unroll
    for (int k = 0; k < EPT; k++)
        if (d[k] >= 0) atomicAdd(&g_degcnt[d[k]], 1);
}

// fused (R5 structure): blocks [0,17): scan stage 1 (local scan + block sums + dinv0);
//                       blocks [17,..): xw0 = dinv0[n]*(x(graph0)@W1), dinv0 from degcnt
__global__ void k_scan1_xw0(const float* __restrict__ data, const float* __restrict__ W1) {
    __shared__ int sh[1024];
    __shared__ float W1s[FIN * H1DIM];
    int tid = threadIdx.x;
    if ((int)blockIdx.x < NSCANB) {
        int idx = blockIdx.x * 1024 + tid;
        int v = (idx < N_NODES) ? g_degcnt[idx] : 0;
        if (idx < N_NODES) g_dinv0[idx] = rsqrtf(1.0f + (float)v);
        sh[tid] = v;
        __syncthreads();
        for (int off = 1; off < 1024; off <<= 1) {
            int t = (tid >= off) ? sh[tid - off] : 0;
            __syncthreads();
            sh[tid] += t;
            __syncthreads();
        }
        if (idx < N_NODES) g_off[idx] = sh[tid] - v;
        if (tid == 1023) g_blksum[blockIdx.x] = sh[1023];
    } else {
        for (int i = tid; i < FIN * H1DIM; i += 1024) W1s[i] = W1[i];
        __syncthreads();
        int node = (blockIdx.x - NSCANB) * 16 + (tid >> 6);
        int c = tid & 63;
        if (node < N_NODES) {
            // degcnt is final after k_count; scan does NOT reset it (k_h1 does)
            float dvi = rsqrtf(1.0f + (float)g_degcnt[node]);
            float acc = 0.f;
            #pragma unroll
            for (int k = 0; k < FIN; k++) acc += data[node * FIN + k] * W1s[k * H1DIM + c];
            g_xw0[node * 64 + ((c & 31) * 2 + (c >> 5))] = dvi * acc;
        }
    }
}

// scan stage 2: each block redundantly warp-scans block sums, adds prefix
__global__ void k_scan3() {
    __shared__ int sPrefix;
    int tid = threadIdx.x;
    if (tid < 32) {
        int v = (tid < NSCANB) ? g_blksum[tid] : 0;
        int inc = v;
        #pragma unroll
        for (int off = 1; off < 32; off <<= 1) {
            int t = __shfl_up_sync(0xffffffffu, inc, off);
            if (tid >= off) inc += t;
        }
        if (tid == (int)blockIdx.x) sPrefix = inc - v;
        if (blockIdx.x == 0 && tid == NSCANB - 1) g_off[N_NODES] = inc;
    }
    __syncthreads();
    int idx = blockIdx.x * 1024 + tid;
    if (idx < N_NODES) g_off[idx] += sPrefix;
}

// 4 edges/thread: batch dst+src loads (MLP), then atomic+store per edge
__global__ void k_scatter(const void* ei) {
    bool is64 = detect64(ei);
    int base = (blockIdx.x * blockDim.x + threadIdx.x) * EPT;
    int d[EPT], s[EPT];
    #pragma unroll
    for (int k = 0; k < EPT; k++) {
        int e = base + k;
        bool v = e < NEDGE;
        d[k] = v ? eidx(ei, is64, (long long)NEDGE + e) : -1;
        s[k] = v ? eidx(ei, is64, e) : 0;
    }
    #pragma unroll
    for (int k = 0; k < EPT; k++) {
        if (d[k] >= 0) {
            int pos = g_off[d[k]] + atomicAdd(&g_cursor[d[k]], 1);
            g_csr[pos] = s[k];
        }
    }
}

// h1 = relu(dvi*(self+msg)+b1); s0w = dinv0*(h1@Wp); resets cursor+degcnt
__global__ void k_h1(const float* __restrict__ b1, const float* __restrict__ Wp) {
    int w = (blockIdx.x * blockDim.x + threadIdx.x) >> 5;
    int lane = threadIdx.x & 31;
    if (w >= N_NODES) return;
    float dvi = g_dinv0[w];
    float2 xw = *(const float2*)(g_xw0 + w * 64 + lane * 2);
    float a0 = xw.x;
    float a1 = xw.y;
    int s = g_off[w], e = g_off[w + 1];
    if (lane == 0) { g_cursor[w] = 0; g_degcnt[w] = 0; }
    int sr_next = (s < e) ? g_csr[s] : 0;
    for (int j = s; j < e; j++) {
        int sr = sr_next;
        if (j + 1 < e) sr_next = g_csr[j + 1];
        float2 m = *(const float2*)(g_xw0 + sr * 64 + lane * 2);
        a0 += m.x;
        a1 += m.y;
    }
    a0 = fmaxf(fmaf(dvi, a0, b1[lane]), 0.f);
    a1 = fmaxf(fmaf(dvi, a1, b1[32 + lane]), 0.f);
    g_h1[w * 64 + lane] = a0;
    g_h1[w * 64 + 32 + lane] = a1;
    float p = a0 * Wp[lane] + a1 * Wp[32 + lane];
    #pragma unroll
    for (int off = 16; off >= 1; off >>= 1) p += __shfl_xor_sync(0xffffffffu, p, off);
    if (lane == 0) g_s0w[w] = dvi * p;
}

// fused (both feed k_select): blocks [0,S0B) graph-0 score msg-pass (prescaled);
//                             blocks [S0B,..) graphs 1..63 scores
__global__ void k_score(const float* __restrict__ data, const float* __restrict__ W1,
                        const float* __restrict__ b1, const float* __restrict__ Wp,
                        const float* __restrict__ bp) {
    int tid = threadIdx.x;
    if ((int)blockIdx.x < S0B) {
        int w = (blockIdx.x * 256 + tid) >> 5;
        int lane = tid & 31;
        if (w >= N_NODES) return;
        float part = 0.f;
        int s = g_off[w], e = g_off[w + 1];
        for (int j = s + lane; j < e; j += 32) part += g_s0w[g_csr[j]];
        #pragma unroll
        for (int off = 16; off >= 1; off >>= 1) part += __shfl_xor_sync(0xffffffffu, part, off);
        if (lane == 0) {
            float dvi = g_dinv0[w];
            g_score[w] = fmaf(dvi, part + g_s0w[w], bp[0]);
        }
        return;
    }
    __shared__ __align__(16) float W1s[FIN * H1DIM];
    __shared__ __align__(16) float b1s[H1DIM];
    __shared__ __align__(16) float Wps[H1DIM];
    for (int i = tid; i < FIN * H1DIM; i += 256) W1s[i] = W1[i];
    if (tid < H1DIM) { b1s[tid] = b1[tid]; Wps[tid] = Wp[tid]; }
    __syncthreads();
    int gid = (blockIdx.x - S0B) * 256 + tid;
    if (gid >= 63 * N_NODES) return;
    int n = N_NODES + gid;
    const float* xr = data + (long long)n * FIN;
    ull xb[6];
    #pragma unroll
    for (int f = 0; f < FIN; f++) { float x = xr[f]; xb[f] = pack2(x, x); }
    const ull* W1p = reinterpret_cast<const ull*>(W1s);
    const ull* b1p = reinterpret_cast<const ull*>(b1s);
    const ull* Wpp = reinterpret_cast<const ull*>(Wps);
    ull acc2 = 0;
    #pragma unroll 4
    for (int c2 = 0; c2 < 32; c2++) {
        ull h2 = b1p[c2];
        #pragma unroll
        for (int f = 0; f < FIN; f++) ffma2(h2, xb[f], W1p[f * 32 + c2]);
        float h0, h1; unpack2(h2, h0, h1);
        h0 = fmaxf(h0, 0.f); h1 = fmaxf(h1, 0.f);
        ull hr = pack2(h0, h1);
        ffma2(acc2, hr, Wpp[c2]);
    }
    float a0, a1; unpack2(acc2, a0, a1);
    g_score[n] = a0 + a1 + bp[0];
}

// per-graph top-K: fixed 3-pass radix (11/11/10), tiny final candidate list
__global__ void k_select() {
    int b = blockIdx.x;
    const float* sc = g_score + (long long)b * N_NODES;
    __shared__ int hist[2048];
    __shared__ int wsum[32];
    __shared__ unsigned sh_pref;
    __shared__ int sh_need;
    __shared__ int eqn;
    __shared__ ull eql[4096];
    int tid = threadIdx.x;
    int lane = tid & 31, wid = tid >> 5;
    unsigned prefix = 0;
    int need = KTOP;
    #pragma unroll
    for (int p = 0; p < 3; p++) {
        const int shift = (p == 0) ? 21 : (p == 1) ? 10 : 0;
        const int width = (p == 2) ? 10 : 11;
        hist[tid] = 0; hist[tid + 1024] = 0;
        __syncthreads();
        for (int i = tid; i < N_NODES; i += 1024) {
            unsigned u = okey(sc[i]);
            bool ok = (p == 0) || ((u >> (shift + width)) == prefix);
            if (ok) atomicAdd(&hist[(u >> shift) & ((1u << width) - 1u)], 1);
        }
        __syncthreads();
        int v0 = 2047 - 2 * tid, v1 = 2046 - 2 * tid;
        int h0 = hist[v0], h1 = hist[v1];
        int local = h0 + h1;
        int inc = local;
        #pragma unroll
        for (int o = 1; o < 32; o <<= 1) {
            int t2 = __shfl_up_sync(0xffffffffu, inc, o);
            if (lane >= o) inc += t2;
        }
        if (lane == 31) wsum[wid] = inc;
        __syncthreads();
        if (tid < 32) {
            int w = wsum[tid];
            int wi = w;
            #pragma unroll
            for (int o = 1; o < 32; o <<= 1) {
                int t2 = __shfl_up_sync(0xffffffffu, wi, o);
                if (tid >= o) wi += t2;
            }
            wsum[tid] = wi - w;
        }
        __syncthreads();
        int prevP = wsum[wid] + (inc - local);
        if (prevP < need && need <= prevP + h0) {
            sh_pref = (prefix << width) | (unsigned)v0;
            sh_need = need - prevP;
        } else if (prevP + h0 < need && need <= prevP + h0 + h1) {
            sh_pref = (prefix << width) | (unsigned)v1;
            sh_need = need - prevP - h0;
        }
        __syncthreads();
        prefix = sh_pref;
        need = sh_need;
        __syncthreads();
    }
    unsigned tau = prefix;
    if (tid == 0) eqn = 0;
    __syncthreads();
    for (int i = tid; i < N_NODES; i += 1024) {
        unsigned u = okey(sc[i]);
        unsigned char k = 0;
        if (u > tau) k = 1;
        else if (u == tau) {
            int p = atomicAdd(&eqn, 1);
            if (p < 4096) eql[p] = ((ull)u << 32) | (unsigned)(0x7FFFFFFF - i);
        }
        g_kept[(long long)b * N_NODES + i] = k;
    }
    __syncthreads();
    int ne = min(eqn, 4096);
    for (int t = tid; t < ne; t += 1024) {
        ull me = eql[t];
        int rank = 0;
        for (int j = 0; j < ne; j++) rank += (eql[j] > me);
        if (rank < need) {
            int idx = 0x7FFFFFFF - (int)(me & 0xFFFFFFFFu);
            g_kept[(long long)b * N_NODES + idx] = 1;
        }
    }
}

// fused: y==0 -> graph-0 dinv2 + xpw = dinv2*tanh(score)*(h1@W2); y>=1 -> compaction
__global__ void k_cx(const float* __restrict__ W2) {
    int tid = threadIdx.x;
    if (blockIdx.y > 0) {
        int nig = blockIdx.x * blockDim.x + tid;
        int bg = blockIdx.y;
        bool kp = (nig < N_NODES) && g_kept[bg * N_NODES + nig];
        unsigned mask = __ballot_sync(0xffffffffu, kp);
        if (!mask) return;
        int lane = tid & 31;
        int leader = __ffs(mask) - 1;
        int base = 0;
        if (lane == leader) base = atomicAdd(&g_knum[bg], __popc(mask));
        base = __shfl_sync(0xffffffffu, base, leader);
        if (kp) {
            int pos = base + __popc(mask & ((1u << lane) - 1u));
            g_kidx[(bg - 1) * KTOP + pos] = nig;
        }
        return;
    }
    __shared__ __align__(16) float W2s[H1DIM * H2DIM];
    for (int i = tid; i < H1DIM * H2DIM; i += 256) W2s[i] = W2[i];
    __syncthreads();
    int n = blockIdx.x * blockDim.x + tid;
    if (n >= N_NODES) return;
    if (!g_kept[n]) {
        g_dinv2[n] = 0.f;
        #pragma unroll
        for (int c = 0; c < H2DIM; c++) g_xpw[n * H2DIM + c] = 0.f;
        return;
    }
    float dvi2;
    {
        int cnt = 0;
        int s = g_off[n], e = g_off[n + 1];
        for (int j = s; j < e; j++) cnt += g_kept[g_csr[j]];
        dvi2 = rsqrtf(1.0f + (float)cnt);
        g_dinv2[n] = dvi2;
    }
    float t = dvi2 * tanhf(g_score[n]);
    const ull* W2p = reinterpret_cast<const ull*>(W2s);
    ull acc2[16];
    #pragma unroll
    for (int c2 = 0; c2 < 16; c2++) acc2[c2] = 0;
    const float4* hr = (const float4*)(g_h1 + n * H1DIM);
    #pragma unroll 4
    for (int k4 = 0; k4 < 16; k4++) {
        float4 h4 = hr[k4];
        ull hb0 = pack2(h4.x, h4.x), hb1 = pack2(h4.y, h4.y);
        ull hb2 = pack2(h4.z, h4.z), hb3 = pack2(h4.w, h4.w);
        const ull* w = W2p + (k4 * 4) * 16;
        #pragma unroll
        for (int c2 = 0; c2 < 16; c2++) {
            ffma2(acc2[c2], hb0, w[c2]);
            ffma2(acc2[c2], hb1, w[16 + c2]);
            ffma2(acc2[c2], hb2, w[32 + c2]);
            ffma2(acc2[c2], hb3, w[48 + c2]);
        }
    }
    #pragma unroll
    for (int c2 = 0; c2 < 16; c2++) {
        float lo, hi; unpack2(acc2[c2], lo, hi);
        g_xpw[n * H2DIM + 2 * c2] = t * lo;
        g_xpw[n * H2DIM + 2 * c2 + 1] = t * hi;
    }
}

// graph 0 conv2 + relu + max-pool into g_gmax[0..31]; xpw pre-scaled
__global__ void k_h2_0(const float* __restrict__ b2) {
    __shared__ int smax[H2DIM];
    int tid = threadIdx.x;
    if (tid < H2DIM) smax[tid] = 0;
    __syncthreads();
    int w = blockIdx.x * 8 + (tid >> 5);
    int lane = tid & 31;
    float v = 0.f;
    if (w < N_NODES && g_kept[w]) {
        float dvi = g_dinv2[w];
        float acc = g_xpw[w * H2DIM + lane];
        int s = g_off[w], e = g_off[w + 1];
        for (int j = s; j < e; j++) acc += g_xpw[g_csr[j] * H2DIM + lane];
        v = fmaxf(fmaf(dvi, acc, b2[lane]), 0.f);
    }
    atomicMax(&smax[lane], __float_as_int(v));
    __syncthreads();
    if (tid < H2DIM)
        atomicMax(reinterpret_cast<int*>(&g_gmax[tid]), smax[tid]);
}

// graphs 1..63: HMMA (mma.sync bf16, split precision) 128x32x64 per CTA
__global__ void k_rest_mma(const float* __restrict__ data, const float* __restrict__ W1,
                           const float* __restrict__ b1, const float* __restrict__ W2,
                           const float* __restrict__ b2) {
    __shared__ __align__(16) __nv_bfloat16 Ah[128 * ASTRIDE];
    __shared__ __align__(16) __nv_bfloat16 Al[128 * ASTRIDE];
    __shared__ __align__(16) float W2s[H1DIM * H2DIM];
    __shared__ __align__(16) float W1s[FIN * H1DIM];
    __shared__ __align__(16) float b1s[H1DIM];
    __shared__ float b2s[H2DIM];
    __shared__ int smax[H2DIM];

    int tid = threadIdx.x, wid = tid >> 5, lane = tid & 31;
    for (int i = tid; i < FIN * H1DIM; i += 128) W1s[i] = W1[i];
    if (tid < H1DIM) b1s[tid] = b1[tid];
    if (tid < H2DIM) { b2s[tid] = b2[tid]; smax[tid] = 0; }
    for (int i = tid; i < H1DIM * H2DIM; i += 128) W2s[i] = W2[i];

    int i0 = blockIdx.x * 128;
    int bg = blockIdx.y + 1;
    bool valid = (i0 + tid) < KTOP;
    int n = bg * N_NODES + (valid ? g_kidx[(bg - 1) * KTOP + i0 + tid] : 0);
    float t = valid ? tanhf(g_score[n]) : 0.f;
    const float* xr = data + (long long)n * FIN;
    ull xb[6];
    #pragma unroll
    for (int f = 0; f < FIN; f++) { float x = xr[f]; xb[f] = pack2(x, x); }
    __syncthreads();

    const ull* W1p = reinterpret_cast<const ull*>(W1s);
    const ull* b1p = reinterpret_cast<const ull*>(b1s);
    char* ahrow = reinterpret_cast<char*>(Ah) + tid * (ASTRIDE * 2);
    char* alrow = reinterpret_cast<char*>(Al) + tid * (ASTRIDE * 2);
    #pragma unroll 4
    for (int k2 = 0; k2 < 32; k2++) {
        ull h2 = b1p[k2];
        #pragma unroll
        for (int f = 0; f < FIN; f++) ffma2(h2, xb[f], W1p[f * 32 + k2]);
        float h0, h1; unpack2(h2, h0, h1);
        h0 = fmaxf(h0, 0.f) * t;
        h1 = fmaxf(h1, 0.f) * t;
        uint32_t hi = bfpack(h0, h1);
        float r0 = h0 - __uint_as_float(hi << 16);
        float r1 = h1 - __uint_as_float(hi & 0xFFFF0000u);
        uint32_t lo = bfpack(r0, r1);
        *reinterpret_cast<uint32_t*>(ahrow + k2 * 4) = hi;
        *reinterpret_cast<uint32_t*>(alrow + k2 * 4) = lo;
    }
    __syncthreads();

    float acc[2][4][4];
    #pragma unroll
    for (int mt = 0; mt < 2; mt++)
        #pragma unroll
        for (int nt = 0; nt < 4; nt++)
            #pragma unroll
            for (int r = 0; r < 4; r++) acc[mt][nt][r] = 0.f;

    int lrow = (lane & 7) + ((lane >> 3) & 1) * 8;
    int khalf = lane >> 4;
    int q = lane & 3, rg = lane >> 2;
    uint32_t ah_base = smem_u32(Ah), al_base = smem_u32(Al);

    #pragma unroll
    for (int kt = 0; kt < 4; kt++) {
        uint32_t af[2][4], alf[2][4];
        #pragma unroll
        for (int mt = 0; mt < 2; mt++) {
            uint32_t off = (wid * 32 + mt * 16 + lrow) * (ASTRIDE * 2) + kt * 32 + khalf * 16;
            ldmat4(af[mt], ah_base + off);
            ldmat4(alf[mt], al_base + off);
        }
        uint32_t bh[4][2], bl[4][2];
        #pragma unroll
        for (int nt = 0; nt < 4; nt++) {
            int col = nt * 8 + rg;
            #pragma unroll
            for (int h = 0; h < 2; h++) {
                int k0 = kt * 16 + 2 * q + h * 8;
                float w0 = W2s[k0 * H2DIM + col];
                float w1 = W2s[(k0 + 1) * H2DIM + col];
                uint32_t hi = bfpack(w0, w1);
                float r0 = w0 - __uint_as_float(hi << 16);
                float r1 = w1 - __uint_as_float(hi & 0xFFFF0000u);
                bh[nt][h] = hi;
                bl[nt][h] = bfpack(r0, r1);
            }
        }
        #pragma unroll
        for (int mt = 0; mt < 2; mt++)
            #pragma unroll
            for (int nt = 0; nt < 4; nt++) {
                mma_bf16(acc[mt][nt], af[mt], bh[nt]);
                mma_bf16(acc[mt][nt], af[mt], bl[nt]);
                mma_bf16(acc[mt][nt], alf[mt], bh[nt]);
            }
    }

    #pragma unroll
    for (int nt = 0; nt < 4; nt++) {
        int col0 = nt * 8 + 2 * q;
        float me = 0.f, mo = 0.f;
        #pragma unroll
        for (int mt = 0; mt < 2; mt++) {
            int r0 = i0 + wid * 32 + mt * 16 + rg;
            bool v0 = r0 < KTOP, v1 = (r0 + 8) < KTOP;
            float e0 = v0 ? fmaxf(acc[mt][nt][0] + b2s[col0], 0.f) : 0.f;
            float e1 = v0 ? fmaxf(acc[mt][nt][1] + b2s[col0 + 1], 0.f) : 0.f;
            float e2 = v1 ? fmaxf(acc[mt][nt][2] + b2s[col0], 0.f) : 0.f;
            float e3 = v1 ? fmaxf(acc[mt][nt][3] + b2s[col0 + 1], 0.f) : 0.f;
            me = fmaxf(me, fmaxf(e0, e2));
            mo = fmaxf(mo, fmaxf(e1, e3));
        }
        #pragma unroll
        for (int off = 4; off < 32; off <<= 1) {
            me = fmaxf(me, __shfl_xor_sync(0xffffffffu, me, off));
            mo = fmaxf(mo, __shfl_xor_sync(0xffffffffu, mo, off));
        }
        if (rg == 0) {
            atomicMax(&smax[col0], __float_as_int(me));
            atomicMax(&smax[col0 + 1], __float_as_int(mo));
        }
    }
    __syncthreads();
    if (tid < H2DIM)
        atomicMax(reinterpret_cast<int*>(&g_gmax[bg * H2DIM + tid]), smax[tid]);
}

__global__ void k_final(const float* __restrict__ Wf, const float* __restrict__ bf,
                        float* __restrict__ out) {
    int b = threadIdx.x;
    if (b >= BATCH) return;
    float acc = bf[0];
    #pragma unroll
    for (int c = 0; c < H2DIM; c++) acc += g_gmax[b * H2DIM + c] * Wf[c];
    out[b] = 1.f / (1.f + expf(-acc));
    #pragma unroll
    for (int c = 0; c < H2DIM; c++) g_gmax[b * H2DIM + c] = 0.f;
    g_knum[b] = 0;
}

// ---------------- launch (R9 skeleton, unchanged) ----------------
extern "C" void kernel_launch(void* const* d_in, const int* in_sizes, int n_in,
                              void* d_out, int out_size) {
    const float* data = (const float*)d_in[0];
    const void*  ei   = d_in[1];
    const float* W1   = (const float*)d_in[2];
    const float* b1   = (const float*)d_in[3];
    const float* Wp   = (const float*)d_in[4];
    const float* bp   = (const float*)d_in[5];
    const float* W2   = (const float*)d_in[6];
    const float* b2   = (const float*)d_in[7];
    const float* Wf   = (const float*)d_in[8];
    const float* bf   = (const float*)d_in[9];
    float* out = (float*)d_out;

    k_count<<<CNT4B, 256>>>(ei);
    k_scan1_xw0<<<NSCANB + XW0B, 1024>>>(data, W1);
    k_scan3<<<NSCANB, 1024>>>();
    k_scatter<<<CNT4B, 256>>>(ei);
    k_h1<<<H1B, 256>>>(b1, Wp);
    k_score<<<S0B + SRB, 256>>>(data, W1, b1, Wp, bp);
    k_select<<<BATCH, 1024>>>();
    k_cx<<<dim3(CXB, BATCH), 256>>>(W2);
    k_h2_0<<<(N_NODES + 7) / 8, 256>>>(b2);
    k_rest_mma<<<dim3(RESTB, 63), 128>>>(data, W1, b1, W2, b2);
    k_final<<<1, 64>>>(Wf, bf, out);
}

// round 11
// speedup vs baseline: 1.0220x; 1.0220x over previous
#include <cuda_runtime.h>
#include <cuda_bf16.h>
#include <cstdint>

#define N_NODES 17186
#define KTOP    12031
#define BATCH   64
#define NEDGE   500000
#define NTOT    (BATCH * N_NODES)
#define FIN     6
#define H1DIM   64
#define H2DIM   32
#define NSCANB  ((N_NODES + 1023) / 1024)            // 17
#define CNTB    ((NEDGE + 255) / 256)                // 1954
#define XW0B    ((N_NODES + 15) / 16)                // 1075 (16 nodes per 1024-thr block)
#define H1B     ((N_NODES + 7) / 8)                  // 2149
#define S0B     ((N_NODES + 7) / 8)                  // 2149
#define SRB     ((63 * N_NODES + 255) / 256)         // 4230
#define CXB     ((N_NODES + 255) / 256)              // 68
#define RESTB   ((KTOP + 127) / 128)                 // 94
#define ASTRIDE 72

typedef unsigned long long ull;

// ---------------- device scratch (zero-init at load; each run restores its
// own invariants so graph replays see identical state) ----------------
__device__ int   g_degcnt[N_NODES];        // reset by k_h1 (after all readers)
__device__ int   g_off[N_NODES + 1];
__device__ int   g_eslot[NEDGE];           // per-edge within-node slot (from k_count)
__device__ int   g_csr[NEDGE];
__device__ int   g_blksum[32];             // fully overwritten each run
__device__ float g_dinv0[N_NODES];
__device__ float g_xw0[N_NODES * H1DIM];   // dinv0[n]*(x@W1), interleaved [n][lane*2+half]
__device__ float g_h1[N_NODES * H1DIM];    // relu(gcn1), standard [n][c]
__device__ float g_s0w[N_NODES];           // dinv0[n]*(h1@Wp)
__device__ float g_score[NTOT];
__device__ unsigned char g_kept[NTOT];
__device__ int   g_knum[BATCH];            // reset by k_final
__device__ int   g_kidx[63 * KTOP];
__device__ float g_dinv2[N_NODES];
__device__ float g_xpw[N_NODES * H2DIM];   // dinv2[n]*tanh(score)*(h1@W2)
__device__ float g_gmax[BATCH * H2DIM];    // reset by k_final

// ---------------- helpers ----------------
__device__ __forceinline__ bool detect64(const void* ei) {
    const long long* p = (const long long*)ei;
    bool ok = true;
    #pragma unroll
    for (int j = 0; j < 8; j++) {
        long long v = p[j];
        if (v < 0 || v >= N_NODES) ok = false;
    }
    return ok;
}
__device__ __forceinline__ int eidx(const void* ei, bool is64, long long pos) {
    if (is64) return (int)((const long long*)ei)[pos];
    return ((const int*)ei)[pos];
}
__device__ __forceinline__ unsigned okey(float f) {
    unsigned u = __float_as_uint(f);
    u ^= (u & 0x80000000u) ? 0xFFFFFFFFu : 0x80000000u;
    return u;
}
__device__ __forceinline__ ull pack2(float lo, float hi) {
    ull r; asm("mov.b64 %0, {%1, %2};" : "=l"(r) : "f"(lo), "f"(hi)); return r;
}
__device__ __forceinline__ void unpack2(ull v, float& lo, float& hi) {
    asm("mov.b64 {%0, %1}, %2;" : "=f"(lo), "=f"(hi) : "l"(v));
}
__device__ __forceinline__ void ffma2(ull& d, ull a, ull b) {
    asm("fma.rn.f32x2 %0, %1, %2, %0;" : "+l"(d) : "l"(a), "l"(b));
}
__device__ __forceinline__ uint32_t smem_u32(const void* p) {
    uint32_t a;
    asm("{ .reg .u64 t; cvta.to.shared.u64 t, %1; cvt.u32.u64 %0, t; }" : "=r"(a) : "l"(p));
    return a;
}
__device__ __forceinline__ uint32_t bfpack(float a, float b) {
    uint32_t r;
    asm("cvt.rn.bf16x2.f32 %0, %1, %2;" : "=r"(r) : "f"(b), "f"(a));
    return r;
}
__device__ __forceinline__ void mma_bf16(float* c, const uint32_t* a, const uint32_t* b) {
    asm volatile(
        "mma.sync.aligned.m16n8k16.row.col.f32.bf16.bf16.f32 "
        "{%0,%1,%2,%3}, {%4,%5,%6,%7}, {%8,%9}, {%0,%1,%2,%3};"
        : "+f"(c[0]), "+f"(c[1]), "+f"(c[2]), "+f"(c[3])
        : "r"(a[0]), "r"(a[1]), "r"(a[2]), "r"(a[3]), "r"(b[0]), "r"(b[1]));
}
__device__ __forceinline__ void ldmat4(uint32_t* a, uint32_t addr) {
    asm volatile("ldmatrix.sync.aligned.m8n8.x4.shared.b16 {%0,%1,%2,%3}, [%4];"
                 : "=r"(a[0]), "=r"(a[1]), "=r"(a[2]), "=r"(a[3]) : "r"(addr));
}

// ---------------- kernels ----------------
// counts degree AND records per-edge slot (atomicAdd return value)
__global__ void k_count(const void* ei) {
    bool is64 = detect64(ei);
    int e = blockIdx.x * blockDim.x + threadIdx.x;
    if (e < NEDGE) {
        int d = eidx(ei, is64, (long long)NEDGE + e);
        g_eslot[e] = atomicAdd(&g_degcnt[d], 1);
    }
}

// fused: blocks [0,17): scan stage 1 (local scan + block sums + dinv0);
//        blocks [17,..): xw0 = dinv0[n]*(x(graph0)@W1), dinv0 from degcnt
__global__ void k_scan1_xw0(const float* __restrict__ data, const float* __restrict__ W1) {
    __shared__ int sh[1024];
    __shared__ float W1s[FIN * H1DIM];
    int tid = threadIdx.x;
    if ((int)blockIdx.x < NSCANB) {
        int idx = blockIdx.x * 1024 + tid;
        int v = (idx < N_NODES) ? g_degcnt[idx] : 0;
        if (idx < N_NODES) g_dinv0[idx] = rsqrtf(1.0f + (float)v);
        sh[tid] = v;
        __syncthreads();
        for (int off = 1; off < 1024; off <<= 1) {
            int t = (tid >= off) ? sh[tid - off] : 0;
            __syncthreads();
            sh[tid] += t;
            __syncthreads();
        }
        if (idx < N_NODES) g_off[idx] = sh[tid] - v;
        if (tid == 1023) g_blksum[blockIdx.x] = sh[1023];
    } else {
        for (int i = tid; i < FIN * H1DIM; i += 1024) W1s[i] = W1[i];
        __syncthreads();
        int node = (blockIdx.x - NSCANB) * 16 + (tid >> 6);
        int c = tid & 63;
        if (node < N_NODES) {
            float dvi = rsqrtf(1.0f + (float)g_degcnt[node]);
            float acc = 0.f;
            #pragma unroll
            for (int k = 0; k < FIN; k++) acc += data[node * FIN + k] * W1s[k * H1DIM + c];
            g_xw0[node * 64 + ((c & 31) * 2 + (c >> 5))] = dvi * acc;
        }
    }
}

// scan stage 2: each block redundantly warp-scans block sums, adds prefix
__global__ void k_scan3() {
    __shared__ int sPrefix;
    int tid = threadIdx.x;
    if (tid < 32) {
        int v = (tid < NSCANB) ? g_blksum[tid] : 0;
        int inc = v;
        #pragma unroll
        for (int off = 1; off < 32; off <<= 1) {
            int t = __shfl_up_sync(0xffffffffu, inc, off);
            if (tid >= off) inc += t;
        }
        if (tid == (int)blockIdx.x) sPrefix = inc - v;
        if (blockIdx.x == 0 && tid == NSCANB - 1) g_off[N_NODES] = inc;
    }
    __syncthreads();
    int idx = blockIdx.x * 1024 + tid;
    if (idx < N_NODES) g_off[idx] += sPrefix;
}

// ATOMIC-FREE scatter: pos = off[dst] + eslot[e]
__global__ void k_scatter(const void* ei) {
    bool is64 = detect64(ei);
    int e = blockIdx.x * blockDim.x + threadIdx.x;
    if (e < NEDGE) {
        int d = eidx(ei, is64, (long long)NEDGE + e);
        int s = eidx(ei, is64, e);
        int slot = g_eslot[e];
        g_csr[g_off[d] + slot] = s;
    }
}

// h1 = relu(dvi*(self+msg)+b1); s0w = dinv0*(h1@Wp); resets degcnt
__global__ void k_h1(const float* __restrict__ b1, const float* __restrict__ Wp) {
    int w = (blockIdx.x * blockDim.x + threadIdx.x) >> 5;
    int lane = threadIdx.x & 31;
    if (w >= N_NODES) return;
    float dvi = g_dinv0[w];
    float2 xw = *(const float2*)(g_xw0 + w * 64 + lane * 2);
    float a0 = xw.x;
    float a1 = xw.y;
    int s = g_off[w], e = g_off[w + 1];
    if (lane == 0) g_degcnt[w] = 0;
    int sr_next = (s < e) ? g_csr[s] : 0;
    for (int j = s; j < e; j++) {
        int sr = sr_next;
        if (j + 1 < e) sr_next = g_csr[j + 1];
        float2 m = *(const float2*)(g_xw0 + sr * 64 + lane * 2);
        a0 += m.x;
        a1 += m.y;
    }
    a0 = fmaxf(fmaf(dvi, a0, b1[lane]), 0.f);
    a1 = fmaxf(fmaf(dvi, a1, b1[32 + lane]), 0.f);
    g_h1[w * 64 + lane] = a0;
    g_h1[w * 64 + 32 + lane] = a1;
    float p = a0 * Wp[lane] + a1 * Wp[32 + lane];
    #pragma unroll
    for (int off = 16; off >= 1; off >>= 1) p += __shfl_xor_sync(0xffffffffu, p, off);
    if (lane == 0) g_s0w[w] = dvi * p;
}

// fused (both feed k_select): blocks [0,S0B) graph-0 score msg-pass (prescaled);
//                             blocks [S0B,..) graphs 1..63 scores
__global__ void k_score(const float* __restrict__ data, const float* __restrict__ W1,
                        const float* __restrict__ b1, const float* __restrict__ Wp,
                        const float* __restrict__ bp) {
    int tid = threadIdx.x;
    if ((int)blockIdx.x < S0B) {
        int w = (blockIdx.x * 256 + tid) >> 5;
        int lane = tid & 31;
        if (w >= N_NODES) return;
        float part = 0.f;
        int s = g_off[w], e = g_off[w + 1];
        for (int j = s + lane; j < e; j += 32) part += g_s0w[g_csr[j]];
        #pragma unroll
        for (int off = 16; off >= 1; off >>= 1) part += __shfl_xor_sync(0xffffffffu, part, off);
        if (lane == 0) {
            float dvi = g_dinv0[w];
            g_score[w] = fmaf(dvi, part + g_s0w[w], bp[0]);
        }
        return;
    }
    __shared__ __align__(16) float W1s[FIN * H1DIM];
    __shared__ __align__(16) float b1s[H1DIM];
    __shared__ __align__(16) float Wps[H1DIM];
    for (int i = tid; i < FIN * H1DIM; i += 256) W1s[i] = W1[i];
    if (tid < H1DIM) { b1s[tid] = b1[tid]; Wps[tid] = Wp[tid]; }
    __syncthreads();
    int gid = (blockIdx.x - S0B) * 256 + tid;
    if (gid >= 63 * N_NODES) return;
    int n = N_NODES + gid;
    const float* xr = data + (long long)n * FIN;
    ull xb[6];
    #pragma unroll
    for (int f = 0; f < FIN; f++) { float x = xr[f]; xb[f] = pack2(x, x); }
    const ull* W1p = reinterpret_cast<const ull*>(W1s);
    const ull* b1p = reinterpret_cast<const ull*>(b1s);
    const ull* Wpp = reinterpret_cast<const ull*>(Wps);
    ull acc2 = 0;
    #pragma unroll 4
    for (int c2 = 0; c2 < 32; c2++) {
        ull h2 = b1p[c2];
        #pragma unroll
        for (int f = 0; f < FIN; f++) ffma2(h2, xb[f], W1p[f * 32 + c2]);
        float h0, h1; unpack2(h2, h0, h1);
        h0 = fmaxf(h0, 0.f); h1 = fmaxf(h1, 0.f);
        ull hr = pack2(h0, h1);
        ffma2(acc2, hr, Wpp[c2]);
    }
    float a0, a1; unpack2(acc2, a0, a1);
    g_score[n] = a0 + a1 + bp[0];
}

// per-graph top-K: fixed 3-pass radix (11/11/10), tiny final candidate list
__global__ void k_select() {
    int b = blockIdx.x;
    const float* sc = g_score + (long long)b * N_NODES;
    __shared__ int hist[2048];
    __shared__ int wsum[32];
    __shared__ unsigned sh_pref;
    __shared__ int sh_need;
    __shared__ int eqn;
    __shared__ ull eql[4096];
    int tid = threadIdx.x;
    int lane = tid & 31, wid = tid >> 5;
    unsigned prefix = 0;
    int need = KTOP;
    #pragma unroll
    for (int p = 0; p < 3; p++) {
        const int shift = (p == 0) ? 21 : (p == 1) ? 10 : 0;
        const int width = (p == 2) ? 10 : 11;
        hist[tid] = 0; hist[tid + 1024] = 0;
        __syncthreads();
        for (int i = tid; i < N_NODES; i += 1024) {
            unsigned u = okey(sc[i]);
            bool ok = (p == 0) || ((u >> (shift + width)) == prefix);
            if (ok) atomicAdd(&hist[(u >> shift) & ((1u << width) - 1u)], 1);
        }
        __syncthreads();
        int v0 = 2047 - 2 * tid, v1 = 2046 - 2 * tid;
        int h0 = hist[v0], h1 = hist[v1];
        int local = h0 + h1;
        int inc = local;
        #pragma unroll
        for (int o = 1; o < 32; o <<= 1) {
            int t2 = __shfl_up_sync(0xffffffffu, inc, o);
            if (lane >= o) inc += t2;
        }
        if (lane == 31) wsum[wid] = inc;
        __syncthreads();
        if (tid < 32) {
            int w = wsum[tid];
            int wi = w;
            #pragma unroll
            for (int o = 1; o < 32; o <<= 1) {
                int t2 = __shfl_up_sync(0xffffffffu, wi, o);
                if (tid >= o) wi += t2;
            }
            wsum[tid] = wi - w;
        }
        __syncthreads();
        int prevP = wsum[wid] + (inc - local);
        if (prevP < need && need <= prevP + h0) {
            sh_pref = (prefix << width) | (unsigned)v0;
            sh_need = need - prevP;
        } else if (prevP + h0 < need && need <= prevP + h0 + h1) {
            sh_pref = (prefix << width) | (unsigned)v1;
            sh_need = need - prevP - h0;
        }
        __syncthreads();
        prefix = sh_pref;
        need = sh_need;
        __syncthreads();
    }
    unsigned tau = prefix;
    if (tid == 0) eqn = 0;
    __syncthreads();
    for (int i = tid; i < N_NODES; i += 1024) {
        unsigned u = okey(sc[i]);
        unsigned char k = 0;
        if (u > tau) k = 1;
        else if (u == tau) {
            int p = atomicAdd(&eqn, 1);
            if (p < 4096) eql[p] = ((ull)u << 32) | (unsigned)(0x7FFFFFFF - i);
        }
        g_kept[(long long)b * N_NODES + i] = k;
    }
    __syncthreads();
    int ne = min(eqn, 4096);
    for (int t = tid; t < ne; t += 1024) {
        ull me = eql[t];
        int rank = 0;
        for (int j = 0; j < ne; j++) rank += (eql[j] > me);
        if (rank < need) {
            int idx = 0x7FFFFFFF - (int)(me & 0xFFFFFFFFu);
            g_kept[(long long)b * N_NODES + idx] = 1;
        }
    }
}

// fused: y==0 -> graph-0 dinv2 + xpw = dinv2*tanh(score)*(h1@W2); y>=1 -> compaction
__global__ void k_cx(const float* __restrict__ W2) {
    int tid = threadIdx.x;
    if (blockIdx.y > 0) {
        int nig = blockIdx.x * blockDim.x + tid;
        int bg = blockIdx.y;
        bool kp = (nig < N_NODES) && g_kept[bg * N_NODES + nig];
        unsigned mask = __ballot_sync(0xffffffffu, kp);
        if (!mask) return;
        int lane = tid & 31;
        int leader = __ffs(mask) - 1;
        int base = 0;
        if (lane == leader) base = atomicAdd(&g_knum[bg], __popc(mask));
        base = __shfl_sync(0xffffffffu, base, leader);
        if (kp) {
            int pos = base + __popc(mask & ((1u << lane) - 1u));
            g_kidx[(bg - 1) * KTOP + pos] = nig;
        }
        return;
    }
    __shared__ __align__(16) float W2s[H1DIM * H2DIM];
    for (int i = tid; i < H1DIM * H2DIM; i += 256) W2s[i] = W2[i];
    __syncthreads();
    int n = blockIdx.x * blockDim.x + tid;
    if (n >= N_NODES) return;
    if (!g_kept[n]) {
        g_dinv2[n] = 0.f;
        #pragma unroll
        for (int c = 0; c < H2DIM; c++) g_xpw[n * H2DIM + c] = 0.f;
        return;
    }
    float dvi2;
    {
        int cnt = 0;
        int s = g_off[n], e = g_off[n + 1];
        for (int j = s; j < e; j++) cnt += g_kept[g_csr[j]];
        dvi2 = rsqrtf(1.0f + (float)cnt);
        g_dinv2[n] = dvi2;
    }
    float t = dvi2 * tanhf(g_score[n]);
    const ull* W2p = reinterpret_cast<const ull*>(W2s);
    ull acc2[16];
    #pragma unroll
    for (int c2 = 0; c2 < 16; c2++) acc2[c2] = 0;
    const float4* hr = (const float4*)(g_h1 + n * H1DIM);
    #pragma unroll 4
    for (int k4 = 0; k4 < 16; k4++) {
        float4 h4 = hr[k4];
        ull hb0 = pack2(h4.x, h4.x), hb1 = pack2(h4.y, h4.y);
        ull hb2 = pack2(h4.z, h4.z), hb3 = pack2(h4.w, h4.w);
        const ull* w = W2p + (k4 * 4) * 16;
        #pragma unroll
        for (int c2 = 0; c2 < 16; c2++) {
            ffma2(acc2[c2], hb0, w[c2]);
            ffma2(acc2[c2], hb1, w[16 + c2]);
            ffma2(acc2[c2], hb2, w[32 + c2]);
            ffma2(acc2[c2], hb3, w[48 + c2]);
        }
    }
    #pragma unroll
    for (int c2 = 0; c2 < 16; c2++) {
        float lo, hi; unpack2(acc2[c2], lo, hi);
        g_xpw[n * H2DIM + 2 * c2] = t * lo;
        g_xpw[n * H2DIM + 2 * c2 + 1] = t * hi;
    }
}

// graph 0 conv2 + relu + max-pool into g_gmax[0..31]; xpw pre-scaled
__global__ void k_h2_0(const float* __restrict__ b2) {
    __shared__ int smax[H2DIM];
    int tid = threadIdx.x;
    if (tid < H2DIM) smax[tid] = 0;
    __syncthreads();
    int w = blockIdx.x * 8 + (tid >> 5);
    int lane = tid & 31;
    float v = 0.f;
    if (w < N_NODES && g_kept[w]) {
        float dvi = g_dinv2[w];
        float acc = g_xpw[w * H2DIM + lane];
        int s = g_off[w], e = g_off[w + 1];
        for (int j = s; j < e; j++) acc += g_xpw[g_csr[j] * H2DIM + lane];
        v = fmaxf(fmaf(dvi, acc, b2[lane]), 0.f);
    }
    atomicMax(&smax[lane], __float_as_int(v));
    __syncthreads();
    if (tid < H2DIM)
        atomicMax(reinterpret_cast<int*>(&g_gmax[tid]), smax[tid]);
}

// graphs 1..63: HMMA (mma.sync bf16, split precision) 128x32x64 per CTA
__global__ void k_rest_mma(const float* __restrict__ data, const float* __restrict__ W1,
                           const float* __restrict__ b1, const float* __restrict__ W2,
                           const float* __restrict__ b2) {
    __shared__ __align__(16) __nv_bfloat16 Ah[128 * ASTRIDE];
    __shared__ __align__(16) __nv_bfloat16 Al[128 * ASTRIDE];
    __shared__ __align__(16) float W2s[H1DIM * H2DIM];
    __shared__ __align__(16) float W1s[FIN * H1DIM];
    __shared__ __align__(16) float b1s[H1DIM];
    __shared__ float b2s[H2DIM];
    __shared__ int smax[H2DIM];

    int tid = threadIdx.x, wid = tid >> 5, lane = tid & 31;
    for (int i = tid; i < FIN * H1DIM; i += 128) W1s[i] = W1[i];
    if (tid < H1DIM) b1s[tid] = b1[tid];
    if (tid < H2DIM) { b2s[tid] = b2[tid]; smax[tid] = 0; }
    for (int i = tid; i < H1DIM * H2DIM; i += 128) W2s[i] = W2[i];

    int i0 = blockIdx.x * 128;
    int bg = blockIdx.y + 1;
    bool valid = (i0 + tid) < KTOP;
    int n = bg * N_NODES + (valid ? g_kidx[(bg - 1) * KTOP + i0 + tid] : 0);
    float t = valid ? tanhf(g_score[n]) : 0.f;
    const float* xr = data + (long long)n * FIN;
    ull xb[6];
    #pragma unroll
    for (int f = 0; f < FIN; f++) { float x = xr[f]; xb[f] = pack2(x, x); }
    __syncthreads();

    const ull* W1p = reinterpret_cast<const ull*>(W1s);
    const ull* b1p = reinterpret_cast<const ull*>(b1s);
    char* ahrow = reinterpret_cast<char*>(Ah) + tid * (ASTRIDE * 2);
    char* alrow = reinterpret_cast<char*>(Al) + tid * (ASTRIDE * 2);
    #pragma unroll 4
    for (int k2 = 0; k2 < 32; k2++) {
        ull h2 = b1p[k2];
        #pragma unroll
        for (int f = 0; f < FIN; f++) ffma2(h2, xb[f], W1p[f * 32 + k2]);
        float h0, h1; unpack2(h2, h0, h1);
        h0 = fmaxf(h0, 0.f) * t;
        h1 = fmaxf(h1, 0.f) * t;
        uint32_t hi = bfpack(h0, h1);
        float r0 = h0 - __uint_as_float(hi << 16);
        float r1 = h1 - __uint_as_float(hi & 0xFFFF0000u);
        uint32_t lo = bfpack(r0, r1);
        *reinterpret_cast<uint32_t*>(ahrow + k2 * 4) = hi;
        *reinterpret_cast<uint32_t*>(alrow + k2 * 4) = lo;
    }
    __syncthreads();

    float acc[2][4][4];
    #pragma unroll
    for (int mt = 0; mt < 2; mt++)
        #pragma unroll
        for (int nt = 0; nt < 4; nt++)
            #pragma unroll
            for (int r = 0; r < 4; r++) acc[mt][nt][r] = 0.f;

    int lrow = (lane & 7) + ((lane >> 3) & 1) * 8;
    int khalf = lane >> 4;
    int q = lane & 3, rg = lane >> 2;
    uint32_t ah_base = smem_u32(Ah), al_base = smem_u32(Al);

    #pragma unroll
    for (int kt = 0; kt < 4; kt++) {
        uint32_t af[2][4], alf[2][4];
        #pragma unroll
        for (int mt = 0; mt < 2; mt++) {
            uint32_t off = (wid * 32 + mt * 16 + lrow) * (ASTRIDE * 2) + kt * 32 + khalf * 16;
            ldmat4(af[mt], ah_base + off);
            ldmat4(alf[mt], al_base + off);
        }
        uint32_t bh[4][2], bl[4][2];
        #pragma unroll
        for (int nt = 0; nt < 4; nt++) {
            int col = nt * 8 + rg;
            #pragma unroll
            for (int h = 0; h < 2; h++) {
                int k0 = kt * 16 + 2 * q + h * 8;
                float w0 = W2s[k0 * H2DIM + col];
                float w1 = W2s[(k0 + 1) * H2DIM + col];
                uint32_t hi = bfpack(w0, w1);
                float r0 = w0 - __uint_as_float(hi << 16);
                float r1 = w1 - __uint_as_float(hi & 0xFFFF0000u);
                bh[nt][h] = hi;
                bl[nt][h] = bfpack(r0, r1);
            }
        }
        #pragma unroll
        for (int mt = 0; mt < 2; mt++)
            #pragma unroll
            for (int nt = 0; nt < 4; nt++) {
                mma_bf16(acc[mt][nt], af[mt], bh[nt]);
                mma_bf16(acc[mt][nt], af[mt], bl[nt]);
                mma_bf16(acc[mt][nt], alf[mt], bh[nt]);
            }
    }

    #pragma unroll
    for (int nt = 0; nt < 4; nt++) {
        int col0 = nt * 8 + 2 * q;
        float me = 0.f, mo = 0.f;
        #pragma unroll
        for (int mt = 0; mt < 2; mt++) {
            int r0 = i0 + wid * 32 + mt * 16 + rg;
            bool v0 = r0 < KTOP, v1 = (r0 + 8) < KTOP;
            float e0 = v0 ? fmaxf(acc[mt][nt][0] + b2s[col0], 0.f) : 0.f;
            float e1 = v0 ? fmaxf(acc[mt][nt][1] + b2s[col0 + 1], 0.f) : 0.f;
            float e2 = v1 ? fmaxf(acc[mt][nt][2] + b2s[col0], 0.f) : 0.f;
            float e3 = v1 ? fmaxf(acc[mt][nt][3] + b2s[col0 + 1], 0.f) : 0.f;
            me = fmaxf(me, fmaxf(e0, e2));
            mo = fmaxf(mo, fmaxf(e1, e3));
        }
        #pragma unroll
        for (int off = 4; off < 32; off <<= 1) {
            me = fmaxf(me, __shfl_xor_sync(0xffffffffu, me, off));
            mo = fmaxf(mo, __shfl_xor_sync(0xffffffffu, mo, off));
        }
        if (rg == 0) {
            atomicMax(&smax[col0], __float_as_int(me));
            atomicMax(&smax[col0 + 1], __float_as_int(mo));
        }
    }
    __syncthreads();
    if (tid < H2DIM)
        atomicMax(reinterpret_cast<int*>(&g_gmax[bg * H2DIM + tid]), smax[tid]);
}

__global__ void k_final(const float* __restrict__ Wf, const float* __restrict__ bf,
                        float* __restrict__ out) {
    int b = threadIdx.x;
    if (b >= BATCH) return;
    float acc = bf[0];
    #pragma unroll
    for (int c = 0; c < H2DIM; c++) acc += g_gmax[b * H2DIM + c] * Wf[c];
    out[b] = 1.f / (1.f + expf(-acc));
    #pragma unroll
    for (int c = 0; c < H2DIM; c++) g_gmax[b * H2DIM + c] = 0.f;
    g_knum[b] = 0;
}

// ---------------- launch (R9 skeleton, unchanged) ----------------
extern "C" void kernel_launch(void* const* d_in, const int* in_sizes, int n_in,
                              void* d_out, int out_size) {
    const float* data = (const float*)d_in[0];
    const void*  ei   = d_in[1];
    const float* W1   = (const float*)d_in[2];
    const float* b1   = (const float*)d_in[3];
    const float* Wp   = (const float*)d_in[4];
    const float* bp   = (const float*)d_in[5];
    const float* W2   = (const float*)d_in[6];
    const float* b2   = (const float*)d_in[7];
    const float* Wf   = (const float*)d_in[8];
    const float* bf   = (const float*)d_in[9];
    float* out = (float*)d_out;

    k_count<<<CNTB, 256>>>(ei);
    k_scan1_xw0<<<NSCANB + XW0B, 1024>>>(data, W1);
    k_scan3<<<NSCANB, 1024>>>();
    k_scatter<<<CNTB, 256>>>(ei);
    k_h1<<<H1B, 256>>>(b1, Wp);
    k_score<<<S0B + SRB, 256>>>(data, W1, b1, Wp, bp);
    k_select<<<BATCH, 1024>>>();
    k_cx<<<dim3(CXB, BATCH), 256>>>(W2);
    k_h2_0<<<(N_NODES + 7) / 8, 256>>>(b2);
    k_rest_mma<<<dim3(RESTB, 63), 128>>>(data, W1, b1, W2, b2);
    k_final<<<1, 64>>>(Wf, bf, out);
}

// round 12
// speedup vs baseline: 1.0226x; 1.0006x over previous
#include <cuda_runtime.h>
#include <cuda_bf16.h>
#include <cstdint>

#define N_NODES 17186
#define KTOP    12031
#define BATCH   64
#define NEDGE   500000
#define NTOT    (BATCH * N_NODES)
#define FIN     6
#define H1DIM   64
#define H2DIM   32
#define NSCANB  ((N_NODES + 1023) / 1024)            // 17
#define CNTB2   ((NEDGE / 2 + 255) / 256)            // 977 (EPT=2 count)
#define CNTB    ((NEDGE + 255) / 256)                // 1954
#define XW0B    ((N_NODES + 15) / 16)                // 1075 (16 nodes per 1024-thr block)
#define H1B     ((N_NODES + 7) / 8)                  // 2149
#define S0B     ((N_NODES + 7) / 8)                  // 2149
#define SRB     ((63 * N_NODES + 255) / 256)         // 4230
#define CXB     ((N_NODES + 255) / 256)              // 68
#define RESTB   ((KTOP + 127) / 128)                 // 94
#define ASTRIDE 72

typedef unsigned long long ull;

// ---------------- device scratch (zero-init at load; each run restores its
// own invariants so graph replays see identical state) ----------------
__device__ int   g_degcnt[N_NODES];        // reset by k_h1 (after all readers)
__device__ int   g_off[N_NODES + 1];
__device__ int   g_eslot[NEDGE];           // per-edge within-node slot (from k_count)
__device__ int   g_csr[NEDGE];
__device__ int   g_blksum[32];             // fully overwritten each run
__device__ float g_dinv0[N_NODES];
__device__ float g_xw0[N_NODES * H1DIM];   // dinv0[n]*(x@W1), interleaved [n][lane*2+half]
__device__ float g_h1[N_NODES * H1DIM];    // relu(gcn1), standard [n][c]
__device__ float g_s0w[N_NODES];           // dinv0[n]*(h1@Wp)
__device__ float g_score[NTOT];
__device__ unsigned char g_kept[NTOT];
__device__ int   g_knum[BATCH];            // reset by k_final
__device__ int   g_kidx[63 * KTOP];
__device__ float g_dinv2[N_NODES];
__device__ float g_xpw[N_NODES * H2DIM];   // dinv2[n]*tanh(score)*(h1@W2)
__device__ float g_gmax[BATCH * H2DIM];    // reset by k_final

// ---------------- helpers ----------------
__device__ __forceinline__ bool detect64(const void* ei) {
    const long long* p = (const long long*)ei;
    bool ok = true;
    #pragma unroll
    for (int j = 0; j < 8; j++) {
        long long v = p[j];
        if (v < 0 || v >= N_NODES) ok = false;
    }
    return ok;
}
__device__ __forceinline__ int eidx(const void* ei, bool is64, long long pos) {
    if (is64) return (int)((const long long*)ei)[pos];
    return ((const int*)ei)[pos];
}
__device__ __forceinline__ unsigned okey(float f) {
    unsigned u = __float_as_uint(f);
    u ^= (u & 0x80000000u) ? 0xFFFFFFFFu : 0x80000000u;
    return u;
}
__device__ __forceinline__ ull pack2(float lo, float hi) {
    ull r; asm("mov.b64 %0, {%1, %2};" : "=l"(r) : "f"(lo), "f"(hi)); return r;
}
__device__ __forceinline__ void unpack2(ull v, float& lo, float& hi) {
    asm("mov.b64 {%0, %1}, %2;" : "=f"(lo), "=f"(hi) : "l"(v));
}
__device__ __forceinline__ void ffma2(ull& d, ull a, ull b) {
    asm("fma.rn.f32x2 %0, %1, %2, %0;" : "+l"(d) : "l"(a), "l"(b));
}
__device__ __forceinline__ uint32_t smem_u32(const void* p) {
    uint32_t a;
    asm("{ .reg .u64 t; cvta.to.shared.u64 t, %1; cvt.u32.u64 %0, t; }" : "=r"(a) : "l"(p));
    return a;
}
__device__ __forceinline__ uint32_t bfpack(float a, float b) {
    uint32_t r;
    asm("cvt.rn.bf16x2.f32 %0, %1, %2;" : "=r"(r) : "f"(b), "f"(a));
    return r;
}
__device__ __forceinline__ void mma_bf16(float* c, const uint32_t* a, const uint32_t* b) {
    asm volatile(
        "mma.sync.aligned.m16n8k16.row.col.f32.bf16.bf16.f32 "
        "{%0,%1,%2,%3}, {%4,%5,%6,%7}, {%8,%9}, {%0,%1,%2,%3};"
        : "+f"(c[0]), "+f"(c[1]), "+f"(c[2]), "+f"(c[3])
        : "r"(a[0]), "r"(a[1]), "r"(a[2]), "r"(a[3]), "r"(b[0]), "r"(b[1]));
}
__device__ __forceinline__ void ldmat4(uint32_t* a, uint32_t addr) {
    asm volatile("ldmatrix.sync.aligned.m8n8.x4.shared.b16 {%0,%1,%2,%3}, [%4];"
                 : "=r"(a[0]), "=r"(a[1]), "=r"(a[2]), "=r"(a[3]) : "r"(addr));
}

// ---------------- kernels ----------------
// counts degree AND records per-edge slot; EPT=2 for atomic-chain MLP
__global__ void k_count(const void* ei) {
    bool is64 = detect64(ei);
    int base = (blockIdx.x * blockDim.x + threadIdx.x) * 2;
    int d0 = (base < NEDGE) ? eidx(ei, is64, (long long)NEDGE + base) : -1;
    int d1 = (base + 1 < NEDGE) ? eidx(ei, is64, (long long)NEDGE + base + 1) : -1;
    if (d0 >= 0) g_eslot[base] = atomicAdd(&g_degcnt[d0], 1);
    if (d1 >= 0) g_eslot[base + 1] = atomicAdd(&g_degcnt[d1], 1);
}

// fused: blocks [0,17): scan stage 1 (local scan + block sums + dinv0);
//        blocks [17,..): xw0 = dinv0[n]*(x(graph0)@W1), dinv0 from degcnt
__global__ void k_scan1_xw0(const float* __restrict__ data, const float* __restrict__ W1) {
    __shared__ int sh[1024];
    __shared__ float W1s[FIN * H1DIM];
    int tid = threadIdx.x;
    if ((int)blockIdx.x < NSCANB) {
        int idx = blockIdx.x * 1024 + tid;
        int v = (idx < N_NODES) ? g_degcnt[idx] : 0;
        if (idx < N_NODES) g_dinv0[idx] = rsqrtf(1.0f + (float)v);
        sh[tid] = v;
        __syncthreads();
        for (int off = 1; off < 1024; off <<= 1) {
            int t = (tid >= off) ? sh[tid - off] : 0;
            __syncthreads();
            sh[tid] += t;
            __syncthreads();
        }
        if (idx < N_NODES) g_off[idx] = sh[tid] - v;
        if (tid == 1023) g_blksum[blockIdx.x] = sh[1023];
    } else {
        for (int i = tid; i < FIN * H1DIM; i += 1024) W1s[i] = W1[i];
        __syncthreads();
        int node = (blockIdx.x - NSCANB) * 16 + (tid >> 6);
        int c = tid & 63;
        if (node < N_NODES) {
            float dvi = rsqrtf(1.0f + (float)g_degcnt[node]);
            float acc = 0.f;
            #pragma unroll
            for (int k = 0; k < FIN; k++) acc += data[node * FIN + k] * W1s[k * H1DIM + c];
            g_xw0[node * 64 + ((c & 31) * 2 + (c >> 5))] = dvi * acc;
        }
    }
}

// scan stage 2: each block redundantly warp-scans block sums, adds prefix
__global__ void k_scan3() {
    __shared__ int sPrefix;
    int tid = threadIdx.x;
    if (tid < 32) {
        int v = (tid < NSCANB) ? g_blksum[tid] : 0;
        int inc = v;
        #pragma unroll
        for (int off = 1; off < 32; off <<= 1) {
            int t = __shfl_up_sync(0xffffffffu, inc, off);
            if (tid >= off) inc += t;
        }
        if (tid == (int)blockIdx.x) sPrefix = inc - v;
        if (blockIdx.x == 0 && tid == NSCANB - 1) g_off[N_NODES] = inc;
    }
    __syncthreads();
    int idx = blockIdx.x * 1024 + tid;
    if (idx < N_NODES) g_off[idx] += sPrefix;
}

// ATOMIC-FREE scatter: pos = off[dst] + eslot[e]
__global__ void k_scatter(const void* ei) {
    bool is64 = detect64(ei);
    int e = blockIdx.x * blockDim.x + threadIdx.x;
    if (e < NEDGE) {
        int d = eidx(ei, is64, (long long)NEDGE + e);
        int s = eidx(ei, is64, e);
        int slot = g_eslot[e];
        g_csr[g_off[d] + slot] = s;
    }
}

// h1 = relu(dvi*(self+msg)+b1); s0w = dinv0*(h1@Wp); resets degcnt
// 4-way unrolled edge gather (MLP=4 on csr + row loads)
__global__ void k_h1(const float* __restrict__ b1, const float* __restrict__ Wp) {
    int w = (blockIdx.x * blockDim.x + threadIdx.x) >> 5;
    int lane = threadIdx.x & 31;
    if (w >= N_NODES) return;
    float dvi = g_dinv0[w];
    float2 xw = *(const float2*)(g_xw0 + w * 64 + lane * 2);
    float a0 = xw.x;
    float a1 = xw.y;
    int s = g_off[w], e = g_off[w + 1];
    if (lane == 0) g_degcnt[w] = 0;
    int j = s;
    for (; j + 4 <= e; j += 4) {
        int sr0 = g_csr[j], sr1 = g_csr[j + 1], sr2 = g_csr[j + 2], sr3 = g_csr[j + 3];
        float2 m0 = *(const float2*)(g_xw0 + sr0 * 64 + lane * 2);
        float2 m1 = *(const float2*)(g_xw0 + sr1 * 64 + lane * 2);
        float2 m2 = *(const float2*)(g_xw0 + sr2 * 64 + lane * 2);
        float2 m3 = *(const float2*)(g_xw0 + sr3 * 64 + lane * 2);
        a0 += (m0.x + m1.x) + (m2.x + m3.x);
        a1 += (m0.y + m1.y) + (m2.y + m3.y);
    }
    for (; j < e; j++) {
        int sr = g_csr[j];
        float2 m = *(const float2*)(g_xw0 + sr * 64 + lane * 2);
        a0 += m.x;
        a1 += m.y;
    }
    a0 = fmaxf(fmaf(dvi, a0, b1[lane]), 0.f);
    a1 = fmaxf(fmaf(dvi, a1, b1[32 + lane]), 0.f);
    g_h1[w * 64 + lane] = a0;
    g_h1[w * 64 + 32 + lane] = a1;
    float p = a0 * Wp[lane] + a1 * Wp[32 + lane];
    #pragma unroll
    for (int off = 16; off >= 1; off >>= 1) p += __shfl_xor_sync(0xffffffffu, p, off);
    if (lane == 0) g_s0w[w] = dvi * p;
}

// fused (both feed k_select): blocks [0,S0B) graph-0 score msg-pass (prescaled);
//                             blocks [S0B,..) graphs 1..63 scores
__global__ void k_score(const float* __restrict__ data, const float* __restrict__ W1,
                        const float* __restrict__ b1, const float* __restrict__ Wp,
                        const float* __restrict__ bp) {
    int tid = threadIdx.x;
    if ((int)blockIdx.x < S0B) {
        int w = (blockIdx.x * 256 + tid) >> 5;
        int lane = tid & 31;
        if (w >= N_NODES) return;
        float part = 0.f;
        int s = g_off[w], e = g_off[w + 1];
        for (int j = s + lane; j < e; j += 32) part += g_s0w[g_csr[j]];
        #pragma unroll
        for (int off = 16; off >= 1; off >>= 1) part += __shfl_xor_sync(0xffffffffu, part, off);
        if (lane == 0) {
            float dvi = g_dinv0[w];
            g_score[w] = fmaf(dvi, part + g_s0w[w], bp[0]);
        }
        return;
    }
    __shared__ __align__(16) float W1s[FIN * H1DIM];
    __shared__ __align__(16) float b1s[H1DIM];
    __shared__ __align__(16) float Wps[H1DIM];
    for (int i = tid; i < FIN * H1DIM; i += 256) W1s[i] = W1[i];
    if (tid < H1DIM) { b1s[tid] = b1[tid]; Wps[tid] = Wp[tid]; }
    __syncthreads();
    int gid = (blockIdx.x - S0B) * 256 + tid;
    if (gid >= 63 * N_NODES) return;
    int n = N_NODES + gid;
    const float* xr = data + (long long)n * FIN;
    ull xb[6];
    #pragma unroll
    for (int f = 0; f < FIN; f++) { float x = xr[f]; xb[f] = pack2(x, x); }
    const ull* W1p = reinterpret_cast<const ull*>(W1s);
    const ull* b1p = reinterpret_cast<const ull*>(b1s);
    const ull* Wpp = reinterpret_cast<const ull*>(Wps);
    ull acc2 = 0;
    #pragma unroll 4
    for (int c2 = 0; c2 < 32; c2++) {
        ull h2 = b1p[c2];
        #pragma unroll
        for (int f = 0; f < FIN; f++) ffma2(h2, xb[f], W1p[f * 32 + c2]);
        float h0, h1; unpack2(h2, h0, h1);
        h0 = fmaxf(h0, 0.f); h1 = fmaxf(h1, 0.f);
        ull hr = pack2(h0, h1);
        ffma2(acc2, hr, Wpp[c2]);
    }
    float a0, a1; unpack2(acc2, a0, a1);
    g_score[n] = a0 + a1 + bp[0];
}

// per-graph top-K: fixed 3-pass radix (11/11/10), tiny final candidate list
__global__ void k_select() {
    int b = blockIdx.x;
    const float* sc = g_score + (long long)b * N_NODES;
    __shared__ int hist[2048];
    __shared__ int wsum[32];
    __shared__ unsigned sh_pref;
    __shared__ int sh_need;
    __shared__ int eqn;
    __shared__ ull eql[4096];
    int tid = threadIdx.x;
    int lane = tid & 31, wid = tid >> 5;
    unsigned prefix = 0;
    int need = KTOP;
    #pragma unroll
    for (int p = 0; p < 3; p++) {
        const int shift = (p == 0) ? 21 : (p == 1) ? 10 : 0;
        const int width = (p == 2) ? 10 : 11;
        hist[tid] = 0; hist[tid + 1024] = 0;
        __syncthreads();
        for (int i = tid; i < N_NODES; i += 1024) {
            unsigned u = okey(sc[i]);
            bool ok = (p == 0) || ((u >> (shift + width)) == prefix);
            if (ok) atomicAdd(&hist[(u >> shift) & ((1u << width) - 1u)], 1);
        }
        __syncthreads();
        int v0 = 2047 - 2 * tid, v1 = 2046 - 2 * tid;
        int h0 = hist[v0], h1 = hist[v1];
        int local = h0 + h1;
        int inc = local;
        #pragma unroll
        for (int o = 1; o < 32; o <<= 1) {
            int t2 = __shfl_up_sync(0xffffffffu, inc, o);
            if (lane >= o) inc += t2;
        }
        if (lane == 31) wsum[wid] = inc;
        __syncthreads();
        if (tid < 32) {
            int w = wsum[tid];
            int wi = w;
            #pragma unroll
            for (int o = 1; o < 32; o <<= 1) {
                int t2 = __shfl_up_sync(0xffffffffu, wi, o);
                if (tid >= o) wi += t2;
            }
            wsum[tid] = wi - w;
        }
        __syncthreads();
        int prevP = wsum[wid] + (inc - local);
        if (prevP < need && need <= prevP + h0) {
            sh_pref = (prefix << width) | (unsigned)v0;
            sh_need = need - prevP;
        } else if (prevP + h0 < need && need <= prevP + h0 + h1) {
            sh_pref = (prefix << width) | (unsigned)v1;
            sh_need = need - prevP - h0;
        }
        __syncthreads();
        prefix = sh_pref;
        need = sh_need;
        __syncthreads();
    }
    unsigned tau = prefix;
    if (tid == 0) eqn = 0;
    __syncthreads();
    for (int i = tid; i < N_NODES; i += 1024) {
        unsigned u = okey(sc[i]);
        unsigned char k = 0;
        if (u > tau) k = 1;
        else if (u == tau) {
            int p = atomicAdd(&eqn, 1);
            if (p < 4096) eql[p] = ((ull)u << 32) | (unsigned)(0x7FFFFFFF - i);
        }
        g_kept[(long long)b * N_NODES + i] = k;
    }
    __syncthreads();
    int ne = min(eqn, 4096);
    for (int t = tid; t < ne; t += 1024) {
        ull me = eql[t];
        int rank = 0;
        for (int j = 0; j < ne; j++) rank += (eql[j] > me);
        if (rank < need) {
            int idx = 0x7FFFFFFF - (int)(me & 0xFFFFFFFFu);
            g_kept[(long long)b * N_NODES + idx] = 1;
        }
    }
}

// fused: y==0 -> graph-0 dinv2 + xpw = dinv2*tanh(score)*(h1@W2); y>=1 -> compaction
__global__ void k_cx(const float* __restrict__ W2) {
    int tid = threadIdx.x;
    if (blockIdx.y > 0) {
        int nig = blockIdx.x * blockDim.x + tid;
        int bg = blockIdx.y;
        bool kp = (nig < N_NODES) && g_kept[bg * N_NODES + nig];
        unsigned mask = __ballot_sync(0xffffffffu, kp);
        if (!mask) return;
        int lane = tid & 31;
        int leader = __ffs(mask) - 1;
        int base = 0;
        if (lane == leader) base = atomicAdd(&g_knum[bg], __popc(mask));
        base = __shfl_sync(0xffffffffu, base, leader);
        if (kp) {
            int pos = base + __popc(mask & ((1u << lane) - 1u));
            g_kidx[(bg - 1) * KTOP + pos] = nig;
        }
        return;
    }
    __shared__ __align__(16) float W2s[H1DIM * H2DIM];
    for (int i = tid; i < H1DIM * H2DIM; i += 256) W2s[i] = W2[i];
    __syncthreads();
    int n = blockIdx.x * blockDim.x + tid;
    if (n >= N_NODES) return;
    if (!g_kept[n]) {
        g_dinv2[n] = 0.f;
        #pragma unroll
        for (int c = 0; c < H2DIM; c++) g_xpw[n * H2DIM + c] = 0.f;
        return;
    }
    float dvi2;
    {
        int cnt = 0;
        int s = g_off[n], e = g_off[n + 1];
        int j = s;
        for (; j + 4 <= e; j += 4) {
            int c0 = g_csr[j], c1 = g_csr[j + 1], c2 = g_csr[j + 2], c3 = g_csr[j + 3];
            cnt += (int)g_kept[c0] + (int)g_kept[c1] + (int)g_kept[c2] + (int)g_kept[c3];
        }
        for (; j < e; j++) cnt += g_kept[g_csr[j]];
        dvi2 = rsqrtf(1.0f + (float)cnt);
        g_dinv2[n] = dvi2;
    }
    float t = dvi2 * tanhf(g_score[n]);
    const ull* W2p = reinterpret_cast<const ull*>(W2s);
    ull acc2[16];
    #pragma unroll
    for (int c2 = 0; c2 < 16; c2++) acc2[c2] = 0;
    const float4* hr = (const float4*)(g_h1 + n * H1DIM);
    #pragma unroll 4
    for (int k4 = 0; k4 < 16; k4++) {
        float4 h4 = hr[k4];
        ull hb0 = pack2(h4.x, h4.x), hb1 = pack2(h4.y, h4.y);
        ull hb2 = pack2(h4.z, h4.z), hb3 = pack2(h4.w, h4.w);
        const ull* w = W2p + (k4 * 4) * 16;
        #pragma unroll
        for (int c2 = 0; c2 < 16; c2++) {
            ffma2(acc2[c2], hb0, w[c2]);
            ffma2(acc2[c2], hb1, w[16 + c2]);
            ffma2(acc2[c2], hb2, w[32 + c2]);
            ffma2(acc2[c2], hb3, w[48 + c2]);
        }
    }
    #pragma unroll
    for (int c2 = 0; c2 < 16; c2++) {
        float lo, hi; unpack2(acc2[c2], lo, hi);
        g_xpw[n * H2DIM + 2 * c2] = t * lo;
        g_xpw[n * H2DIM + 2 * c2 + 1] = t * hi;
    }
}

// graph 0 conv2 + relu + max-pool; 4-way unrolled xpw gather
__global__ void k_h2_0(const float* __restrict__ b2) {
    __shared__ int smax[H2DIM];
    int tid = threadIdx.x;
    if (tid < H2DIM) smax[tid] = 0;
    __syncthreads();
    int w = blockIdx.x * 8 + (tid >> 5);
    int lane = tid & 31;
    float v = 0.f;
    if (w < N_NODES && g_kept[w]) {
        float dvi = g_dinv2[w];
        float acc = g_xpw[w * H2DIM + lane];
        int s = g_off[w], e = g_off[w + 1];
        int j = s;
        for (; j + 4 <= e; j += 4) {
            int c0 = g_csr[j], c1 = g_csr[j + 1], c2 = g_csr[j + 2], c3 = g_csr[j + 3];
            float m0 = g_xpw[c0 * H2DIM + lane];
            float m1 = g_xpw[c1 * H2DIM + lane];
            float m2 = g_xpw[c2 * H2DIM + lane];
            float m3 = g_xpw[c3 * H2DIM + lane];
            acc += (m0 + m1) + (m2 + m3);
        }
        for (; j < e; j++) acc += g_xpw[g_csr[j] * H2DIM + lane];
        v = fmaxf(fmaf(dvi, acc, b2[lane]), 0.f);
    }
    atomicMax(&smax[lane], __float_as_int(v));
    __syncthreads();
    if (tid < H2DIM)
        atomicMax(reinterpret_cast<int*>(&g_gmax[tid]), smax[tid]);
}

// graphs 1..63: HMMA (mma.sync bf16, split precision) 128x32x64 per CTA
__global__ void k_rest_mma(const float* __restrict__ data, const float* __restrict__ W1,
                           const float* __restrict__ b1, const float* __restrict__ W2,
                           const float* __restrict__ b2) {
    __shared__ __align__(16) __nv_bfloat16 Ah[128 * ASTRIDE];
    __shared__ __align__(16) __nv_bfloat16 Al[128 * ASTRIDE];
    __shared__ __align__(16) float W2s[H1DIM * H2DIM];
    __shared__ __align__(16) float W1s[FIN * H1DIM];
    __shared__ __align__(16) float b1s[H1DIM];
    __shared__ float b2s[H2DIM];
    __shared__ int smax[H2DIM];

    int tid = threadIdx.x, wid = tid >> 5, lane = tid & 31;
    for (int i = tid; i < FIN * H1DIM; i += 128) W1s[i] = W1[i];
    if (tid < H1DIM) b1s[tid] = b1[tid];
    if (tid < H2DIM) { b2s[tid] = b2[tid]; smax[tid] = 0; }
    for (int i = tid; i < H1DIM * H2DIM; i += 128) W2s[i] = W2[i];

    int i0 = blockIdx.x * 128;
    int bg = blockIdx.y + 1;
    bool valid = (i0 + tid) < KTOP;
    int n = bg * N_NODES + (valid ? g_kidx[(bg - 1) * KTOP + i0 + tid] : 0);
    float t = valid ? tanhf(g_score[n]) : 0.f;
    const float* xr = data + (long long)n * FIN;
    ull xb[6];
    #pragma unroll
    for (int f = 0; f < FIN; f++) { float x = xr[f]; xb[f] = pack2(x, x); }
    __syncthreads();

    const ull* W1p = reinterpret_cast<const ull*>(W1s);
    const ull* b1p = reinterpret_cast<const ull*>(b1s);
    char* ahrow = reinterpret_cast<char*>(Ah) + tid * (ASTRIDE * 2);
    char* alrow = reinterpret_cast<char*>(Al) + tid * (ASTRIDE * 2);
    #pragma unroll 4
    for (int k2 = 0; k2 < 32; k2++) {
        ull h2 = b1p[k2];
        #pragma unroll
        for (int f = 0; f < FIN; f++) ffma2(h2, xb[f], W1p[f * 32 + k2]);
        float h0, h1; unpack2(h2, h0, h1);
        h0 = fmaxf(h0, 0.f) * t;
        h1 = fmaxf(h1, 0.f) * t;
        uint32_t hi = bfpack(h0, h1);
        float r0 = h0 - __uint_as_float(hi << 16);
        float r1 = h1 - __uint_as_float(hi & 0xFFFF0000u);
        uint32_t lo = bfpack(r0, r1);
        *reinterpret_cast<uint32_t*>(ahrow + k2 * 4) = hi;
        *reinterpret_cast<uint32_t*>(alrow + k2 * 4) = lo;
    }
    __syncthreads();

    float acc[2][4][4];
    #pragma unroll
    for (int mt = 0; mt < 2; mt++)
        #pragma unroll
        for (int nt = 0; nt < 4; nt++)
            #pragma unroll
            for (int r = 0; r < 4; r++) acc[mt][nt][r] = 0.f;

    int lrow = (lane & 7) + ((lane >> 3) & 1) * 8;
    int khalf = lane >> 4;
    int q = lane & 3, rg = lane >> 2;
    uint32_t ah_base = smem_u32(Ah), al_base = smem_u32(Al);

    #pragma unroll
    for (int kt = 0; kt < 4; kt++) {
        uint32_t af[2][4], alf[2][4];
        #pragma unroll
        for (int mt = 0; mt < 2; mt++) {
            uint32_t off = (wid * 32 + mt * 16 + lrow) * (ASTRIDE * 2) + kt * 32 + khalf * 16;
            ldmat4(af[mt], ah_base + off);
            ldmat4(alf[mt], al_base + off);
        }
        uint32_t bh[4][2], bl[4][2];
        #pragma unroll
        for (int nt = 0; nt < 4; nt++) {
            int col = nt * 8 + rg;
            #pragma unroll
            for (int h = 0; h < 2; h++) {
                int k0 = kt * 16 + 2 * q + h * 8;
                float w0 = W2s[k0 * H2DIM + col];
                float w1 = W2s[(k0 + 1) * H2DIM + col];
                uint32_t hi = bfpack(w0, w1);
                float r0 = w0 - __uint_as_float(hi << 16);
                float r1 = w1 - __uint_as_float(hi & 0xFFFF0000u);
                bh[nt][h] = hi;
                bl[nt][h] = bfpack(r0, r1);
            }
        }
        #pragma unroll
        for (int mt = 0; mt < 2; mt++)
            #pragma unroll
            for (int nt = 0; nt < 4; nt++) {
                mma_bf16(acc[mt][nt], af[mt], bh[nt]);
                mma_bf16(acc[mt][nt], af[mt], bl[nt]);
                mma_bf16(acc[mt][nt], alf[mt], bh[nt]);
            }
    }

    #pragma unroll
    for (int nt = 0; nt < 4; nt++) {
        int col0 = nt * 8 + 2 * q;
        float me = 0.f, mo = 0.f;
        #pragma unroll
        for (int mt = 0; mt < 2; mt++) {
            int r0 = i0 + wid * 32 + mt * 16 + rg;
            bool v0 = r0 < KTOP, v1 = (r0 + 8) < KTOP;
            float e0 = v0 ? fmaxf(acc[mt][nt][0] + b2s[col0], 0.f) : 0.f;
            float e1 = v0 ? fmaxf(acc[mt][nt][1] + b2s[col0 + 1], 0.f) : 0.f;
            float e2 = v1 ? fmaxf(acc[mt][nt][2] + b2s[col0], 0.f) : 0.f;
            float e3 = v1 ? fmaxf(acc[mt][nt][3] + b2s[col0 + 1], 0.f) : 0.f;
            me = fmaxf(me, fmaxf(e0, e2));
            mo = fmaxf(mo, fmaxf(e1, e3));
        }
        #pragma unroll
        for (int off = 4; off < 32; off <<= 1) {
            me = fmaxf(me, __shfl_xor_sync(0xffffffffu, me, off));
            mo = fmaxf(mo, __shfl_xor_sync(0xffffffffu, mo, off));
        }
        if (rg == 0) {
            atomicMax(&smax[col0], __float_as_int(me));
            atomicMax(&smax[col0 + 1], __float_as_int(mo));
        }
    }
    __syncthreads();
    if (tid < H2DIM)
        atomicMax(reinterpret_cast<int*>(&g_gmax[bg * H2DIM + tid]), smax[tid]);
}

__global__ void k_final(const float* __restrict__ Wf, const float* __restrict__ bf,
                        float* __restrict__ out) {
    int b = threadIdx.x;
    if (b >= BATCH) return;
    float acc = bf[0];
    #pragma unroll
    for (int c = 0; c < H2DIM; c++) acc += g_gmax[b * H2DIM + c] * Wf[c];
    out[b] = 1.f / (1.f + expf(-acc));
    #pragma unroll
    for (int c = 0; c < H2DIM; c++) g_gmax[b * H2DIM + c] = 0.f;
    g_knum[b] = 0;
}

// ---------------- launch (frozen skeleton) ----------------
extern "C" void kernel_launch(void* const* d_in, const int* in_sizes, int n_in,
                              void* d_out, int out_size) {
    const float* data = (const float*)d_in[0];
    const void*  ei   = d_in[1];
    const float* W1   = (const float*)d_in[2];
    const float* b1   = (const float*)d_in[3];
    const float* Wp   = (const float*)d_in[4];
    const float* bp   = (const float*)d_in[5];
    const float* W2   = (const float*)d_in[6];
    const float* b2   = (const float*)d_in[7];
    const float* Wf   = (const float*)d_in[8];
    const float* bf   = (const float*)d_in[9];
    float* out = (float*)d_out;

    k_count<<<CNTB2, 256>>>(ei);
    k_scan1_xw0<<<NSCANB + XW0B, 1024>>>(data, W1);
    k_scan3<<<NSCANB, 1024>>>();
    k_scatter<<<CNTB, 256>>>(ei);
    k_h1<<<H1B, 256>>>(b1, Wp);
    k_score<<<S0B + SRB, 256>>>(data, W1, b1, Wp, bp);
    k_select<<<BATCH, 1024>>>();
    k_cx<<<dim3(CXB, BATCH), 256>>>(W2);
    k_h2_0<<<(N_NODES + 7) / 8, 256>>>(b2);
    k_rest_mma<<<dim3(RESTB, 63), 128>>>(data, W1, b1, W2, b2);
    k_final<<<1, 64>>>(Wf, bf, out);
}